// round 7
// baseline (speedup 1.0000x reference)
#include <cuda_runtime.h>
#include <cuda_bf16.h>
#include <math.h>

#define BSZ   512
#define TT    64
#define NF    512
#define HID   1000
#define MAXG  16
#define EPSV  1e-5f
#define BF    (BSZ*NF)

// ---------------- scratch -----------------------------------------------------
__device__ float g_xint[TT*BSZ*NF];
__device__ float g_u   [TT*BSZ*NF];
__device__ float g_hs  [TT*BSZ*NF];
__device__ float g_z1  [TT*BSZ*HID];
__device__ float g_z2  [TT*BSZ*HID];
__device__ float g_y   [TT*BSZ*NF];
__device__ float g_xall[MAXG*BSZ*NF];
__device__ float g_dxh [2*BSZ*1024];
__device__ float g_dz1 [BSZ*HID];
__device__ float g_dz2 [BSZ*HID];
__device__ float g_wc  [512*1024];
__device__ float g_bc  [512];
__device__ float g_a1[HID], g_d1[HID];
__device__ float g_a2[HID], g_d2[HID];
__device__ float g_a3[NF],  g_d3[NF];
__device__ double g_sum1, g_sum2;
__device__ unsigned g_barcnt = 0;
__device__ volatile unsigned g_bargen = 0;

// ---------------- helpers ------------------------------------------------------
__device__ __forceinline__ unsigned f2tf(float f)
{
    unsigned r;
    asm("cvt.rna.tf32.f32 %0, %1;" : "=r"(r) : "f"(f));
    return r;
}

__device__ __forceinline__ void mma_tf32(float* c, const unsigned* a, const unsigned* b)
{
    asm volatile(
        "mma.sync.aligned.m16n8k8.row.col.f32.tf32.tf32.f32 "
        "{%0,%1,%2,%3},{%4,%5,%6,%7},{%8,%9},{%0,%1,%2,%3};"
        : "+f"(c[0]), "+f"(c[1]), "+f"(c[2]), "+f"(c[3])
        : "r"(a[0]), "r"(a[1]), "r"(a[2]), "r"(a[3]), "r"(b[0]), "r"(b[1]));
}

// ---------------- prep ---------------------------------------------------------
__global__ void prep_kernel(const float* __restrict__ x,
    const float* W_ih, const float* W_hh, const float* b_ih, const float* b_hh,
    const float* b1, const float* g1, const float* be1, const float* rm1, const float* rv1,
    const float* b2, const float* g2, const float* be2, const float* rm2, const float* rv2,
    const float* b3, const float* g3, const float* be3, const float* rm3, const float* rv3)
{
    long long idx = (long long)blockIdx.x * blockDim.x + threadIdx.x;
    const long long TOT = (long long)TT * BSZ * NF;
    if (idx < TOT) {
        int f = (int)(idx & (NF - 1));
        long long tb = idx >> 9;
        int b = (int)(tb & (BSZ - 1));
        int t = (int)(tb >> 9);
        g_xint[idx] = x[((long long)b * (TT + 1) + t) * NF + f];
    }
    if (idx < 512 * 1024) {
        int n = (int)(idx >> 10), k = (int)(idx & 1023);
        g_wc[idx] = (k < 512) ? W_ih[n * 512 + k] : W_hh[n * 512 + (k - 512)];
    }
    if (idx < HID) {
        float s1 = g1[idx] * rsqrtf(rv1[idx] + EPSV);
        g_a1[idx] = s1;
        g_d1[idx] = s1 * (b1[idx] - rm1[idx]) + be1[idx];
        float s2 = g2[idx] * rsqrtf(rv2[idx] + EPSV);
        g_a2[idx] = s2;
        g_d2[idx] = s2 * (b2[idx] - rm2[idx]) + be2[idx];
    }
    if (idx < NF) {
        float s3 = g3[idx] * rsqrtf(rv3[idx] + EPSV);
        g_a3[idx] = s3;
        g_d3[idx] = s3 * (b3[idx] - rm3[idx]) + be3[idx];
        g_bc[idx] = b_ih[idx] + b_hh[idx];
    }
    if (idx == 0) { g_sum1 = 0.0; g_sum2 = 0.0; g_barcnt = 0; g_bargen = 0; }
}

// ---------------- tf32 tensor-core GEMM ----------------------------------------
// C[M,N] = f(A[M,lda] @ W[N,ldw]^T). BM == THREADS/2. BK=16.
// PAD=8 -> k-stride (BM+8) == 8 (mod 32): frag loads are bank-conflict-free.
// B staging stores guarded by srow < BN (needed when BN < BM).
template<int BM, int BN, int WM, int WN, bool SCALE, bool TANH, bool DUAL>
__global__ void __launch_bounds__(WM*WN*32) mma_gemm_kernel(
    const float* __restrict__ A, int lda,
    const float* __restrict__ W, int ldw,
    const float* __restrict__ bias, const float* __restrict__ scale,
    float* __restrict__ C, int ldc, float* __restrict__ C2, int ldc2,
    int N, int K)
{
    constexpr int TM = BM / WM;
    constexpr int TN = BN / WN;
    constexpr int FM = TM / 16;
    constexpr int FN = TN / 8;
    constexpr int PAD = 8;

    __shared__ unsigned sA[2][16][BM + PAD];
    __shared__ unsigned sB[2][16][BN + PAD];

    const int tid  = threadIdx.x;
    const int lane = tid & 31;
    const int wid  = tid >> 5;
    const int wm   = wid / WN, wn = wid % WN;
    const int g8   = lane >> 2, t4 = lane & 3;

    const int m0 = blockIdx.y * BM;
    const int n0 = blockIdx.x * BN;

    const int srow = tid >> 1;
    const int skq  = (tid & 1) * 8;
    const float* Ap = A + (long long)(m0 + srow) * lda + skq;
    const bool bstage = srow < BN;                 // guard for BN < BM
    const int brow = n0 + srow;
    const bool bok = bstage && (brow < N);
    const float* Bp = W + (long long)brow * ldw + skq;

    float acc[FM][FN][4];
    #pragma unroll
    for (int i = 0; i < FM; i++)
        #pragma unroll
        for (int j = 0; j < FN; j++)
            #pragma unroll
            for (int q = 0; q < 4; q++) acc[i][j][q] = 0.0f;

    const int nch = (K + 15) >> 4;

    float pa[8], pb[8];
    // prefetch chunk 0
    {
        if (16 <= K) {
            float4 v0 = *(const float4*)Ap, v1 = *(const float4*)(Ap + 4);
            pa[0]=v0.x; pa[1]=v0.y; pa[2]=v0.z; pa[3]=v0.w;
            pa[4]=v1.x; pa[5]=v1.y; pa[6]=v1.z; pa[7]=v1.w;
            if (bok) {
                float4 w0 = *(const float4*)Bp, w1 = *(const float4*)(Bp + 4);
                pb[0]=w0.x; pb[1]=w0.y; pb[2]=w0.z; pb[3]=w0.w;
                pb[4]=w1.x; pb[5]=w1.y; pb[6]=w1.z; pb[7]=w1.w;
            } else {
                #pragma unroll
                for (int q = 0; q < 8; q++) pb[q] = 0.0f;
            }
        } else {
            #pragma unroll
            for (int q = 0; q < 8; q++) {
                int k = skq + q;
                pa[q] = (k < K) ? Ap[q] : 0.0f;
                pb[q] = (bok && k < K) ? Bp[q] : 0.0f;
            }
        }
    }
    #pragma unroll
    for (int q = 0; q < 8; q++) {
        sA[0][skq + q][srow] = f2tf(pa[q]);
        if (bstage) sB[0][skq + q][srow] = f2tf(pb[q]);
    }
    __syncthreads();

    for (int c = 0; c < nch; c++) {
        const int buf = c & 1;
        if (c + 1 < nch) {
            const int kk = (c + 1) * 16;
            if (kk + 16 <= K) {
                float4 v0 = *(const float4*)(Ap + kk), v1 = *(const float4*)(Ap + kk + 4);
                pa[0]=v0.x; pa[1]=v0.y; pa[2]=v0.z; pa[3]=v0.w;
                pa[4]=v1.x; pa[5]=v1.y; pa[6]=v1.z; pa[7]=v1.w;
                if (bok) {
                    float4 w0 = *(const float4*)(Bp + kk), w1 = *(const float4*)(Bp + kk + 4);
                    pb[0]=w0.x; pb[1]=w0.y; pb[2]=w0.z; pb[3]=w0.w;
                    pb[4]=w1.x; pb[5]=w1.y; pb[6]=w1.z; pb[7]=w1.w;
                } else {
                    #pragma unroll
                    for (int q = 0; q < 8; q++) pb[q] = 0.0f;
                }
            } else {
                #pragma unroll
                for (int q = 0; q < 8; q++) {
                    int k = kk + skq + q;
                    pa[q] = (k < K) ? Ap[kk + q] : 0.0f;
                    pb[q] = (bok && k < K) ? Bp[kk + q] : 0.0f;
                }
            }
        }

        #pragma unroll
        for (int ks = 0; ks < 16; ks += 8) {
            unsigned af[FM][4], bf[FN][2];
            #pragma unroll
            for (int i = 0; i < FM; i++) {
                int m = wm * TM + 16 * i + g8;
                af[i][0] = sA[buf][ks + t4][m];
                af[i][1] = sA[buf][ks + t4][m + 8];
                af[i][2] = sA[buf][ks + t4 + 4][m];
                af[i][3] = sA[buf][ks + t4 + 4][m + 8];
            }
            #pragma unroll
            for (int j = 0; j < FN; j++) {
                int n = wn * TN + 8 * j + g8;
                bf[j][0] = sB[buf][ks + t4][n];
                bf[j][1] = sB[buf][ks + t4 + 4][n];
            }
            #pragma unroll
            for (int i = 0; i < FM; i++)
                #pragma unroll
                for (int j = 0; j < FN; j++)
                    mma_tf32(acc[i][j], af[i], bf[j]);
        }

        if (c + 1 < nch) {
            const int nb = buf ^ 1;
            #pragma unroll
            for (int q = 0; q < 8; q++) {
                sA[nb][skq + q][srow] = f2tf(pa[q]);
                if (bstage) sB[nb][skq + q][srow] = f2tf(pb[q]);
            }
        }
        __syncthreads();
    }

    // epilogue
    #pragma unroll
    for (int i = 0; i < FM; i++) {
        int row = m0 + wm * TM + 16 * i + g8;
        #pragma unroll
        for (int j = 0; j < FN; j++) {
            int col = n0 + wn * TN + 8 * j + 2 * t4;
            if (col < N) {
                float2 bi = *(const float2*)(bias + col);
                float2 sc;
                if (SCALE) sc = *(const float2*)(scale + col);
                float v00 = acc[i][j][0], v01 = acc[i][j][1];
                float v10 = acc[i][j][2], v11 = acc[i][j][3];
                if (SCALE) {
                    v00 = v00 * sc.x + bi.x; v01 = v01 * sc.y + bi.y;
                    v10 = v10 * sc.x + bi.x; v11 = v11 * sc.y + bi.y;
                } else {
                    v00 += bi.x; v01 += bi.y; v10 += bi.x; v11 += bi.y;
                }
                if (TANH) { v00 = tanhf(v00); v01 = tanhf(v01);
                            v10 = tanhf(v10); v11 = tanhf(v11); }
                *(float2*)(C + (long long)row * ldc + col)       = make_float2(v00, v01);
                *(float2*)(C + (long long)(row + 8) * ldc + col) = make_float2(v10, v11);
                if (DUAL) {
                    *(float2*)(C2 + (long long)row * ldc2 + col)       = make_float2(v00, v01);
                    *(float2*)(C2 + (long long)(row + 8) * ldc2 + col) = make_float2(v10, v11);
                }
            }
        }
    }
}

// ---------------- persistent scan kernel (FFMA) --------------------------------
__device__ __forceinline__ void grid_barrier(int nb)
{
    __syncthreads();
    if (threadIdx.x == 0) {
        __threadfence();
        unsigned gen = g_bargen;
        if (atomicAdd(&g_barcnt, 1u) == (unsigned)(nb - 1)) {
            g_barcnt = 0;
            __threadfence();
            g_bargen = gen + 1;
        } else {
            while (g_bargen == gen) { }
        }
    }
    __syncthreads();
}

__global__ void __launch_bounds__(256) scan_kernel(const float* __restrict__ Whh,
                                                   const float* __restrict__ bhh)
{
    extern __shared__ float sm[];
    float* sW = sm;               // [512][34]
    float* sA = sm + 512 * 34;    // [2][16][68]

    const int tid = threadIdx.x;
    const int tx = tid & 15, ty = tid >> 4;
    const int n0 = (blockIdx.x & 15) * 32;
    const int m0 = (blockIdx.x >> 4) * 64;

    for (int idx = tid; idx < 32 * 512; idx += 256) {
        int k = idx & 511, n = idx >> 9;
        sW[k * 34 + n] = Whh[(n0 + n) * 512 + k];
    }
    const float bh0 = bhh[n0 + tx * 2];
    const float bh1 = bhh[n0 + tx * 2 + 1];
    __syncthreads();

    const int r = tid >> 2, cq = tid & 3;

    for (int t = 0; t < TT; t++) {
        float acc[4][2] = {};
        if (t > 0) {
            const float* A = g_hs + (long long)(t - 1) * BF + (long long)(m0 + r) * 512 + cq * 4;
            float4 pa = *(const float4*)A;
            {
                float* d = sA + (cq * 4) * 68 + r;
                d[0] = pa.x; d[68] = pa.y; d[136] = pa.z; d[204] = pa.w;
            }
            __syncthreads();
            for (int c = 0; c < 32; c++) {
                const int buf = c & 1;
                if (c + 1 < 32) pa = *(const float4*)(A + (c + 1) * 16);
                const float* bA = sA + buf * 1088;
                const float* bW = sW + (c * 16) * 34 + tx * 2;
                #pragma unroll
                for (int k = 0; k < 16; k++) {
                    float4 a = *(const float4*)(bA + k * 68 + ty * 4);
                    float2 w = *(const float2*)(bW + k * 34);
                    acc[0][0] += a.x * w.x; acc[0][1] += a.x * w.y;
                    acc[1][0] += a.y * w.x; acc[1][1] += a.y * w.y;
                    acc[2][0] += a.z * w.x; acc[2][1] += a.z * w.y;
                    acc[3][0] += a.w * w.x; acc[3][1] += a.w * w.y;
                }
                if (c + 1 < 32) {
                    float* d = sA + (buf ^ 1) * 1088 + (cq * 4) * 68 + r;
                    d[0] = pa.x; d[68] = pa.y; d[136] = pa.z; d[204] = pa.w;
                }
                __syncthreads();
            }
        }
        const float* Ut = g_u + (long long)t * BF;
        float* Ht = g_hs + (long long)t * BF;
        #pragma unroll
        for (int i = 0; i < 4; i++) {
            long long off = (long long)(m0 + ty * 4 + i) * 512 + n0 + tx * 2;
            float2 u = *(const float2*)(Ut + off);
            float2 h;
            h.x = tanhf(acc[i][0] + u.x + bh0);
            h.y = tanhf(acc[i][1] + u.y + bh1);
            *(float2*)(Ht + off) = h;
        }
        grid_barrier(gridDim.x);
    }
}

// ---------------- reductions / misc --------------------------------------------
__device__ __forceinline__ double block_reduce(double v)
{
    __shared__ double sh[32];
    #pragma unroll
    for (int o = 16; o > 0; o >>= 1) v += __shfl_down_sync(0xffffffffu, v, o);
    int lane = threadIdx.x & 31, w = threadIdx.x >> 5;
    if (lane == 0) sh[w] = v;
    __syncthreads();
    if (w == 0) {
        int nw = (blockDim.x + 31) >> 5;
        v = (lane < nw) ? sh[lane] : 0.0;
        #pragma unroll
        for (int o = 16; o > 0; o >>= 1) v += __shfl_down_sync(0xffffffffu, v, o);
    }
    return v;
}

__global__ void loss1_kernel()
{
    const long long TOT = (long long)(TT - 1) * BSZ * NF;
    double local = 0.0;
    for (long long idx = (long long)blockIdx.x * blockDim.x + threadIdx.x;
         idx < TOT; idx += (long long)gridDim.x * blockDim.x) {
        float d = g_y[idx] - g_xint[idx + BF];
        local += (double)d * (double)d;
    }
    double s = block_reduce(local);
    if (threadIdx.x == 0) atomicAdd(&g_sum1, s);
}

__global__ void init_dec_kernel()
{
    int idx = blockIdx.x * blockDim.x + threadIdx.x;
    if (idx < BF) {
        int b = idx >> 9, f = idx & 511;
        g_dxh[(long long)b * 1024 + f]       = g_y [(long long)63 * BF + idx];
        g_dxh[(long long)b * 1024 + 512 + f] = g_hs[(long long)63 * BF + idx];
    }
}

__global__ void finalize_kernel(const float* __restrict__ x,
                                const int* __restrict__ t,
                                float* __restrict__ out)
{
    int b = blockIdx.x;
    int g = t[b] - 1;
    const float* xp = g_xall + ((long long)g * BSZ + b) * NF;
    const float* xf = x + ((long long)b * (TT + 1) + TT) * NF;
    double local = 0.0;
    for (int f = threadIdx.x; f < NF; f += blockDim.x) {
        float v = xp[f];
        out[(long long)b * NF + f] = v;
        float d = v - xf[f];
        local += (double)d * (double)d;
    }
    double s = block_reduce(local);
    if (threadIdx.x == 0) atomicAdd(&g_sum2, s);
}

__global__ void write_loss_kernel(float* __restrict__ out, int out_size)
{
    if (out_size > BSZ * NF) {
        double n1 = (double)(TT - 1) * BSZ * NF;
        double n2 = (double)BSZ * NF;
        double loss = g_sum1 / (n1 * n1) + g_sum2 / (n2 * n2);
        out[BSZ * NF] = (float)loss;
    }
}

// ---------------- launch --------------------------------------------------------
extern "C" void kernel_launch(void* const* d_in, const int* in_sizes, int n_in,
                              void* d_out, int out_size)
{
    const float* x    = (const float*)d_in[0];
    const int*   t    = (const int*)  d_in[1];
    const float* W_ih = (const float*)d_in[2];
    const float* W_hh = (const float*)d_in[3];
    const float* b_ih = (const float*)d_in[4];
    const float* b_hh = (const float*)d_in[5];
    const float* W1   = (const float*)d_in[6];
    const float* b1   = (const float*)d_in[7];
    const float* g1   = (const float*)d_in[8];
    const float* be1  = (const float*)d_in[9];
    const float* rm1  = (const float*)d_in[10];
    const float* rv1  = (const float*)d_in[11];
    const float* W2   = (const float*)d_in[12];
    const float* b2   = (const float*)d_in[13];
    const float* g2   = (const float*)d_in[14];
    const float* be2  = (const float*)d_in[15];
    const float* rm2  = (const float*)d_in[16];
    const float* rv2  = (const float*)d_in[17];
    const float* W3   = (const float*)d_in[18];
    const float* b3   = (const float*)d_in[19];
    const float* g3   = (const float*)d_in[20];
    const float* be3  = (const float*)d_in[21];
    const float* rm3  = (const float*)d_in[22];
    const float* rv3  = (const float*)d_in[23];
    float* out = (float*)d_out;

    float *xint, *u, *hs, *z1, *z2, *y, *xall, *dxh, *dz1, *dz2, *wc, *bc;
    float *a1, *d1, *a2, *d2, *a3, *d3;
    cudaGetSymbolAddress((void**)&xint, g_xint);
    cudaGetSymbolAddress((void**)&u,    g_u);
    cudaGetSymbolAddress((void**)&hs,   g_hs);
    cudaGetSymbolAddress((void**)&z1,   g_z1);
    cudaGetSymbolAddress((void**)&z2,   g_z2);
    cudaGetSymbolAddress((void**)&y,    g_y);
    cudaGetSymbolAddress((void**)&xall, g_xall);
    cudaGetSymbolAddress((void**)&dxh,  g_dxh);
    cudaGetSymbolAddress((void**)&dz1,  g_dz1);
    cudaGetSymbolAddress((void**)&dz2,  g_dz2);
    cudaGetSymbolAddress((void**)&wc,   g_wc);
    cudaGetSymbolAddress((void**)&bc,   g_bc);
    cudaGetSymbolAddress((void**)&a1,   g_a1);
    cudaGetSymbolAddress((void**)&d1,   g_d1);
    cudaGetSymbolAddress((void**)&a2,   g_a2);
    cudaGetSymbolAddress((void**)&d2,   g_d2);
    cudaGetSymbolAddress((void**)&a3,   g_a3);
    cudaGetSymbolAddress((void**)&d3,   g_d3);

    const int scan_smem = (512 * 34 + 2 * 16 * 68) * 4;
    cudaFuncSetAttribute(scan_kernel,
                         cudaFuncAttributeMaxDynamicSharedMemorySize, scan_smem);

    const long long TOT = (long long)TT * BSZ * NF;
    prep_kernel<<<(unsigned)((TOT + 255) / 256), 256>>>(
        x, W_ih, W_hh, b_ih, b_hh,
        b1, g1, be1, rm1, rv1, b2, g2, be2, rm2, rv2, b3, g3, be3, rm3, rv3);

    // U = XIN @ W_ih^T + b_ih
    {
        dim3 grid(NF / 128, (TT * BSZ) / 128);
        mma_gemm_kernel<128,128,2,4,false,false,false><<<grid, 256>>>(
            xint, NF, W_ih, NF, b_ih, nullptr, u, NF, nullptr, 0, NF, NF);
    }

    // persistent scan
    scan_kernel<<<128, 256, scan_smem>>>(W_hh, b_hh);

    // autoencoder over all rows
    {
        dim3 grid1((HID + 127) / 128, (TT * BSZ) / 128);
        mma_gemm_kernel<128,128,2,4,true,false,false><<<grid1, 256>>>(
            hs, NF, W1, NF, d1, a1, z1, HID, nullptr, 0, HID, NF);
        mma_gemm_kernel<128,128,2,4,true,false,false><<<grid1, 256>>>(
            z1, HID, W2, HID, d2, a2, z2, HID, nullptr, 0, HID, HID);
        dim3 grid3(NF / 128, (TT * BSZ) / 128);
        mma_gemm_kernel<128,128,2,4,true,false,false><<<grid3, 256>>>(
            z2, HID, W3, HID, d3, a3, y, NF, nullptr, 0, NF, HID);
    }

    loss1_kernel<<<2048, 256>>>();
    init_dec_kernel<<<(BF + 255) / 256, 256>>>();

    // decoder: 16 steps x 4 mma GEMMs
    {
        dim3 gcell(512 / 32, BSZ / 64);                // 64x32 tiles -> 128 blocks
        dim3 ghid((HID + 63) / 64, BSZ / 64);          // 64x64 tiles -> 128 blocks
        for (int g = 0; g < MAXG; g++) {
            float* cur  = dxh + (size_t)(g & 1) * BSZ * 1024;
            float* next = dxh + (size_t)((g + 1) & 1) * BSZ * 1024;
            mma_gemm_kernel<64,32,1,4,false,true,false><<<gcell, 128>>>(
                cur, 1024, wc, 1024, bc, nullptr, next + 512, 1024, nullptr, 0, 512, 1024);
            mma_gemm_kernel<64,64,1,4,true,false,false><<<ghid, 128>>>(
                next + 512, 1024, W1, NF, d1, a1, dz1, HID, nullptr, 0, HID, NF);
            mma_gemm_kernel<64,64,1,4,true,false,false><<<ghid, 128>>>(
                dz1, HID, W2, HID, d2, a2, dz2, HID, nullptr, 0, HID, HID);
            mma_gemm_kernel<64,32,1,4,true,false,true><<<gcell, 128>>>(
                dz2, HID, W3, HID, d3, a3, next, 1024,
                xall + (size_t)g * BF, NF, 512, HID);
        }
    }

    finalize_kernel<<<BSZ, 256>>>(x, t, out);
    write_loss_kernel<<<1, 1>>>(out, out_size);
}

// round 11
// speedup vs baseline: 1.5995x; 1.5995x over previous
#include <cuda_runtime.h>
#include <cuda_bf16.h>
#include <math.h>

#define BSZ   512
#define TT    64
#define NF    512
#define HID   1000
#define MAXG  16
#define EPSV  1e-5f
#define BF    (BSZ*NF)

// ---------------- scratch -----------------------------------------------------
__device__ __align__(256) float g_xint[TT*BSZ*NF];
__device__ __align__(256) float g_u   [TT*BSZ*NF];
__device__ __align__(256) float g_hs  [TT*BSZ*NF];
__device__ __align__(256) float g_z1  [TT*BSZ*HID];
__device__ __align__(256) float g_z2  [TT*BSZ*HID];
__device__ __align__(256) float g_y   [TT*BSZ*NF];
__device__ __align__(256) float g_xall[MAXG*BSZ*NF];
__device__ __align__(256) float g_dxh [2*BSZ*1024];
__device__ __align__(256) float g_dz1 [BSZ*HID];
__device__ __align__(256) float g_dz2 [BSZ*HID];
__device__ __align__(256) float g_wc  [512*1024];
__device__ __align__(256) float g_bc  [512];
__device__ __align__(16) float g_a1[HID], g_d1[HID];
__device__ __align__(16) float g_a2[HID], g_d2[HID];
__device__ __align__(16) float g_a3[NF],  g_d3[NF];
__device__ double g_sum1, g_sum2;
__device__ unsigned g_barcnt = 0;
__device__ volatile unsigned g_bargen = 0;

// ---------------- helpers ------------------------------------------------------
__device__ __forceinline__ unsigned f2tf(float f)
{
    unsigned r;
    asm("cvt.rna.tf32.f32 %0, %1;" : "=r"(r) : "f"(f));
    return r;
}

__device__ __forceinline__ void mma_tf32(float* c, const unsigned* a, const unsigned* b)
{
    asm volatile(
        "mma.sync.aligned.m16n8k8.row.col.f32.tf32.tf32.f32 "
        "{%0,%1,%2,%3},{%4,%5,%6,%7},{%8,%9},{%0,%1,%2,%3};"
        : "+f"(c[0]), "+f"(c[1]), "+f"(c[2]), "+f"(c[3])
        : "r"(a[0]), "r"(a[1]), "r"(a[2]), "r"(a[3]), "r"(b[0]), "r"(b[1]));
}

__device__ __forceinline__ void cp_async16(unsigned saddr, const void* gptr, int vb)
{
    asm volatile("cp.async.cg.shared.global [%0], [%1], 16, %2;\n"
                 :: "r"(saddr), "l"(gptr), "r"(vb));
}
__device__ __forceinline__ void cp_commit()
{
    asm volatile("cp.async.commit_group;\n" ::: "memory");
}
__device__ __forceinline__ void cp_wait0()
{
    asm volatile("cp.async.wait_group 0;\n" ::: "memory");
}

// ---------------- prep ---------------------------------------------------------
__global__ void prep_kernel(const float* __restrict__ x,
    const float* W_ih, const float* W_hh, const float* b_ih, const float* b_hh,
    const float* b1, const float* g1, const float* be1, const float* rm1, const float* rv1,
    const float* b2, const float* g2, const float* be2, const float* rm2, const float* rv2,
    const float* b3, const float* g3, const float* be3, const float* rm3, const float* rv3)
{
    long long idx = (long long)blockIdx.x * blockDim.x + threadIdx.x;
    const long long TOT = (long long)TT * BSZ * NF;
    if (idx < TOT) {
        int f = (int)(idx & (NF - 1));
        long long tb = idx >> 9;
        int b = (int)(tb & (BSZ - 1));
        int t = (int)(tb >> 9);
        g_xint[idx] = x[((long long)b * (TT + 1) + t) * NF + f];
    }
    if (idx < 512 * 1024) {
        int n = (int)(idx >> 10), k = (int)(idx & 1023);
        g_wc[idx] = (k < 512) ? W_ih[n * 512 + k] : W_hh[n * 512 + (k - 512)];
    }
    if (idx < HID) {
        float s1 = g1[idx] * rsqrtf(rv1[idx] + EPSV);
        g_a1[idx] = s1;
        g_d1[idx] = s1 * (b1[idx] - rm1[idx]) + be1[idx];
        float s2 = g2[idx] * rsqrtf(rv2[idx] + EPSV);
        g_a2[idx] = s2;
        g_d2[idx] = s2 * (b2[idx] - rm2[idx]) + be2[idx];
    }
    if (idx < NF) {
        float s3 = g3[idx] * rsqrtf(rv3[idx] + EPSV);
        g_a3[idx] = s3;
        g_d3[idx] = s3 * (b3[idx] - rm3[idx]) + be3[idx];
        g_bc[idx] = b_ih[idx] + b_hh[idx];
    }
    if (idx == 0) { g_sum1 = 0.0; g_sum2 = 0.0; g_barcnt = 0; g_bargen = 0; }
}

// ---------------- tf32 tensor-core GEMM with cp.async staging -------------------
// C[M,N] = f(A[M,lda] @ W[N,ldw]^T). BK=16, row-major smem tiles, stride 20.
// Raw f32 staged via LDGSTS; cvt.rna.tf32 applied at fragment load (R3 numerics).
template<int BM, int BN, int WM, int WN, bool SCALE, bool TANH, bool DUAL>
__global__ void __launch_bounds__(WM*WN*32) mma_gemm_kernel(
    const float* __restrict__ A, int lda,
    const float* __restrict__ W, int ldw,
    const float* __restrict__ bias, const float* __restrict__ scale,
    float* __restrict__ C, int ldc, float* __restrict__ C2, int ldc2,
    int N, int K)
{
    constexpr int THREADS = WM * WN * 32;
    constexpr int TM = BM / WM;
    constexpr int TN = BN / WN;
    constexpr int FM = TM / 16;
    constexpr int FN = TN / 8;
    constexpr int LDSZ = 20;                       // 16 k + 4 pad; conflict-free frag loads
    constexpr int ASEG = (BM * 4) / THREADS;
    constexpr int BSEG = (BN * 4) / THREADS;
    static_assert(ASEG >= 1 && BSEG >= 1, "tile/thread mismatch");

    __shared__ __align__(16) float sA[2][BM][LDSZ];
    __shared__ __align__(16) float sB[2][BN][LDSZ];

    const int tid  = threadIdx.x;
    const int lane = tid & 31;
    const int wid  = tid >> 5;
    const int wm   = wid / WN, wn = wid % WN;
    const int g8   = lane >> 2, t4 = lane & 3;

    const int m0 = blockIdx.y * BM;
    const int n0 = blockIdx.x * BN;

    const unsigned sA_u = (unsigned)__cvta_generic_to_shared(&sA[0][0][0]);
    const unsigned sB_u = (unsigned)__cvta_generic_to_shared(&sB[0][0][0]);

    int aRow[ASEG], aKq[ASEG];
    const float* aBase[ASEG];
    #pragma unroll
    for (int l = 0; l < ASEG; l++) {
        int s = tid + l * THREADS;
        aRow[l] = s >> 2;
        aKq[l]  = (s & 3) * 4;
        aBase[l] = A + (long long)(m0 + aRow[l]) * lda;
    }
    int bRow[BSEG], bKq[BSEG];
    const float* bBase[BSEG];
    bool bOk[BSEG];
    #pragma unroll
    for (int l = 0; l < BSEG; l++) {
        int s = tid + l * THREADS;
        bRow[l] = s >> 2;
        bKq[l]  = (s & 3) * 4;
        bOk[l]  = (n0 + bRow[l]) < N;
        bBase[l] = W + (long long)(bOk[l] ? (n0 + bRow[l]) : 0) * ldw;
    }

    const int nch = (K + 15) >> 4;

    auto stage = [&](int buf, int kk) {
        #pragma unroll
        for (int l = 0; l < ASEG; l++) {
            int gk = kk + aKq[l];
            int rem = K - gk;
            int vb = rem >= 4 ? 16 : (rem > 0 ? rem * 4 : 0);
            const float* src = aBase[l] + (vb ? gk : 0);
            unsigned dst = sA_u + (((buf * BM + aRow[l]) * LDSZ) + aKq[l]) * 4;
            cp_async16(dst, src, vb);
        }
        #pragma unroll
        for (int l = 0; l < BSEG; l++) {
            int gk = kk + bKq[l];
            int rem = K - gk;
            int vb = (bOk[l] && rem > 0) ? (rem >= 4 ? 16 : rem * 4) : 0;
            const float* src = bBase[l] + (vb ? gk : 0);
            unsigned dst = sB_u + (((buf * BN + bRow[l]) * LDSZ) + bKq[l]) * 4;
            cp_async16(dst, src, vb);
        }
        cp_commit();
    };

    float acc[FM][FN][4];
    #pragma unroll
    for (int i = 0; i < FM; i++)
        #pragma unroll
        for (int j = 0; j < FN; j++)
            #pragma unroll
            for (int q = 0; q < 4; q++) acc[i][j][q] = 0.0f;

    stage(0, 0);

    for (int c = 0; c < nch; c++) {
        const int buf = c & 1;
        cp_wait0();
        __syncthreads();
        if (c + 1 < nch) stage(buf ^ 1, (c + 1) * 16);

        #pragma unroll
        for (int ks = 0; ks < 16; ks += 8) {
            unsigned af[FM][4], bf[FN][2];
            #pragma unroll
            for (int i = 0; i < FM; i++) {
                int m = wm * TM + 16 * i + g8;
                af[i][0] = f2tf(sA[buf][m    ][ks + t4]);
                af[i][1] = f2tf(sA[buf][m + 8][ks + t4]);
                af[i][2] = f2tf(sA[buf][m    ][ks + t4 + 4]);
                af[i][3] = f2tf(sA[buf][m + 8][ks + t4 + 4]);
            }
            #pragma unroll
            for (int j = 0; j < FN; j++) {
                int n = wn * TN + 8 * j + g8;
                bf[j][0] = f2tf(sB[buf][n][ks + t4]);
                bf[j][1] = f2tf(sB[buf][n][ks + t4 + 4]);
            }
            #pragma unroll
            for (int i = 0; i < FM; i++)
                #pragma unroll
                for (int j = 0; j < FN; j++)
                    mma_tf32(acc[i][j], af[i], bf[j]);
        }
    }

    // epilogue
    #pragma unroll
    for (int i = 0; i < FM; i++) {
        int row = m0 + wm * TM + 16 * i + g8;
        #pragma unroll
        for (int j = 0; j < FN; j++) {
            int col = n0 + wn * TN + 8 * j + 2 * t4;
            if (col < N) {
                float2 bi = *(const float2*)(bias + col);
                float2 sc;
                if (SCALE) sc = *(const float2*)(scale + col);
                float v00 = acc[i][j][0], v01 = acc[i][j][1];
                float v10 = acc[i][j][2], v11 = acc[i][j][3];
                if (SCALE) {
                    v00 = v00 * sc.x + bi.x; v01 = v01 * sc.y + bi.y;
                    v10 = v10 * sc.x + bi.x; v11 = v11 * sc.y + bi.y;
                } else {
                    v00 += bi.x; v01 += bi.y; v10 += bi.x; v11 += bi.y;
                }
                if (TANH) { v00 = tanhf(v00); v01 = tanhf(v01);
                            v10 = tanhf(v10); v11 = tanhf(v11); }
                *(float2*)(C + (long long)row * ldc + col)       = make_float2(v00, v01);
                *(float2*)(C + (long long)(row + 8) * ldc + col) = make_float2(v10, v11);
                if (DUAL) {
                    *(float2*)(C2 + (long long)row * ldc2 + col)       = make_float2(v00, v01);
                    *(float2*)(C2 + (long long)(row + 8) * ldc2 + col) = make_float2(v10, v11);
                }
            }
        }
    }
}

// ---------------- persistent scan kernel (FFMA) --------------------------------
__device__ __forceinline__ void grid_barrier(int nb)
{
    __syncthreads();
    if (threadIdx.x == 0) {
        __threadfence();
        unsigned gen = g_bargen;
        if (atomicAdd(&g_barcnt, 1u) == (unsigned)(nb - 1)) {
            g_barcnt = 0;
            __threadfence();
            g_bargen = gen + 1;
        } else {
            while (g_bargen == gen) { }
        }
    }
    __syncthreads();
}

__global__ void __launch_bounds__(256) scan_kernel(const float* __restrict__ Whh,
                                                   const float* __restrict__ bhh)
{
    extern __shared__ float sm[];
    float* sW = sm;               // [512][34]
    float* sA = sm + 512 * 34;    // [2][16][68]

    const int tid = threadIdx.x;
    const int tx = tid & 15, ty = tid >> 4;
    const int n0 = (blockIdx.x & 15) * 32;
    const int m0 = (blockIdx.x >> 4) * 64;

    for (int idx = tid; idx < 32 * 512; idx += 256) {
        int k = idx & 511, n = idx >> 9;
        sW[k * 34 + n] = Whh[(n0 + n) * 512 + k];
    }
    const float bh0 = bhh[n0 + tx * 2];
    const float bh1 = bhh[n0 + tx * 2 + 1];
    __syncthreads();

    const int r = tid >> 2, cq = tid & 3;

    for (int t = 0; t < TT; t++) {
        float acc[4][2] = {};
        if (t > 0) {
            const float* A = g_hs + (long long)(t - 1) * BF + (long long)(m0 + r) * 512 + cq * 4;
            float4 pa = *(const float4*)A;
            {
                float* d = sA + (cq * 4) * 68 + r;
                d[0] = pa.x; d[68] = pa.y; d[136] = pa.z; d[204] = pa.w;
            }
            __syncthreads();
            for (int c = 0; c < 32; c++) {
                const int buf = c & 1;
                if (c + 1 < 32) pa = *(const float4*)(A + (c + 1) * 16);
                const float* bA = sA + buf * 1088;
                const float* bW = sW + (c * 16) * 34 + tx * 2;
                #pragma unroll
                for (int k = 0; k < 16; k++) {
                    float4 a = *(const float4*)(bA + k * 68 + ty * 4);
                    float2 w = *(const float2*)(bW + k * 34);
                    acc[0][0] += a.x * w.x; acc[0][1] += a.x * w.y;
                    acc[1][0] += a.y * w.x; acc[1][1] += a.y * w.y;
                    acc[2][0] += a.z * w.x; acc[2][1] += a.z * w.y;
                    acc[3][0] += a.w * w.x; acc[3][1] += a.w * w.y;
                }
                if (c + 1 < 32) {
                    float* d = sA + (buf ^ 1) * 1088 + (cq * 4) * 68 + r;
                    d[0] = pa.x; d[68] = pa.y; d[136] = pa.z; d[204] = pa.w;
                }
                __syncthreads();
            }
        }
        const float* Ut = g_u + (long long)t * BF;
        float* Ht = g_hs + (long long)t * BF;
        #pragma unroll
        for (int i = 0; i < 4; i++) {
            long long off = (long long)(m0 + ty * 4 + i) * 512 + n0 + tx * 2;
            float2 u = *(const float2*)(Ut + off);
            float2 h;
            h.x = tanhf(acc[i][0] + u.x + bh0);
            h.y = tanhf(acc[i][1] + u.y + bh1);
            *(float2*)(Ht + off) = h;
        }
        grid_barrier(gridDim.x);
    }
}

// ---------------- reductions / misc --------------------------------------------
__device__ __forceinline__ double block_reduce(double v)
{
    __shared__ double sh[32];
    #pragma unroll
    for (int o = 16; o > 0; o >>= 1) v += __shfl_down_sync(0xffffffffu, v, o);
    int lane = threadIdx.x & 31, w = threadIdx.x >> 5;
    if (lane == 0) sh[w] = v;
    __syncthreads();
    if (w == 0) {
        int nw = (blockDim.x + 31) >> 5;
        v = (lane < nw) ? sh[lane] : 0.0;
        #pragma unroll
        for (int o = 16; o > 0; o >>= 1) v += __shfl_down_sync(0xffffffffu, v, o);
    }
    return v;
}

__global__ void loss1_kernel()
{
    const long long TOT = (long long)(TT - 1) * BSZ * NF;
    double local = 0.0;
    for (long long idx = (long long)blockIdx.x * blockDim.x + threadIdx.x;
         idx < TOT; idx += (long long)gridDim.x * blockDim.x) {
        float d = g_y[idx] - g_xint[idx + BF];
        local += (double)d * (double)d;
    }
    double s = block_reduce(local);
    if (threadIdx.x == 0) atomicAdd(&g_sum1, s);
}

__global__ void init_dec_kernel()
{
    int idx = blockIdx.x * blockDim.x + threadIdx.x;
    if (idx < BF) {
        int b = idx >> 9, f = idx & 511;
        g_dxh[(long long)b * 1024 + f]       = g_y [(long long)63 * BF + idx];
        g_dxh[(long long)b * 1024 + 512 + f] = g_hs[(long long)63 * BF + idx];
    }
}

__global__ void finalize_kernel(const float* __restrict__ x,
                                const int* __restrict__ t,
                                float* __restrict__ out)
{
    int b = blockIdx.x;
    int g = t[b] - 1;
    const float* xp = g_xall + ((long long)g * BSZ + b) * NF;
    const float* xf = x + ((long long)b * (TT + 1) + TT) * NF;
    double local = 0.0;
    for (int f = threadIdx.x; f < NF; f += blockDim.x) {
        float v = xp[f];
        out[(long long)b * NF + f] = v;
        float d = v - xf[f];
        local += (double)d * (double)d;
    }
    double s = block_reduce(local);
    if (threadIdx.x == 0) atomicAdd(&g_sum2, s);
}

__global__ void write_loss_kernel(float* __restrict__ out, int out_size)
{
    if (out_size > BSZ * NF) {
        double n1 = (double)(TT - 1) * BSZ * NF;
        double n2 = (double)BSZ * NF;
        double loss = g_sum1 / (n1 * n1) + g_sum2 / (n2 * n2);
        out[BSZ * NF] = (float)loss;
    }
}

// ---------------- launch --------------------------------------------------------
extern "C" void kernel_launch(void* const* d_in, const int* in_sizes, int n_in,
                              void* d_out, int out_size)
{
    const float* x    = (const float*)d_in[0];
    const int*   t    = (const int*)  d_in[1];
    const float* W_ih = (const float*)d_in[2];
    const float* W_hh = (const float*)d_in[3];
    const float* b_ih = (const float*)d_in[4];
    const float* b_hh = (const float*)d_in[5];
    const float* W1   = (const float*)d_in[6];
    const float* b1   = (const float*)d_in[7];
    const float* g1   = (const float*)d_in[8];
    const float* be1  = (const float*)d_in[9];
    const float* rm1  = (const float*)d_in[10];
    const float* rv1  = (const float*)d_in[11];
    const float* W2   = (const float*)d_in[12];
    const float* b2   = (const float*)d_in[13];
    const float* g2   = (const float*)d_in[14];
    const float* be2  = (const float*)d_in[15];
    const float* rm2  = (const float*)d_in[16];
    const float* rv2  = (const float*)d_in[17];
    const float* W3   = (const float*)d_in[18];
    const float* b3   = (const float*)d_in[19];
    const float* g3   = (const float*)d_in[20];
    const float* be3  = (const float*)d_in[21];
    const float* rm3  = (const float*)d_in[22];
    const float* rv3  = (const float*)d_in[23];
    float* out = (float*)d_out;

    float *xint, *u, *hs, *z1, *z2, *y, *xall, *dxh, *dz1, *dz2, *wc, *bc;
    float *a1, *d1, *a2, *d2, *a3, *d3;
    cudaGetSymbolAddress((void**)&xint, g_xint);
    cudaGetSymbolAddress((void**)&u,    g_u);
    cudaGetSymbolAddress((void**)&hs,   g_hs);
    cudaGetSymbolAddress((void**)&z1,   g_z1);
    cudaGetSymbolAddress((void**)&z2,   g_z2);
    cudaGetSymbolAddress((void**)&y,    g_y);
    cudaGetSymbolAddress((void**)&xall, g_xall);
    cudaGetSymbolAddress((void**)&dxh,  g_dxh);
    cudaGetSymbolAddress((void**)&dz1,  g_dz1);
    cudaGetSymbolAddress((void**)&dz2,  g_dz2);
    cudaGetSymbolAddress((void**)&wc,   g_wc);
    cudaGetSymbolAddress((void**)&bc,   g_bc);
    cudaGetSymbolAddress((void**)&a1,   g_a1);
    cudaGetSymbolAddress((void**)&d1,   g_d1);
    cudaGetSymbolAddress((void**)&a2,   g_a2);
    cudaGetSymbolAddress((void**)&d2,   g_d2);
    cudaGetSymbolAddress((void**)&a3,   g_a3);
    cudaGetSymbolAddress((void**)&d3,   g_d3);

    const int scan_smem = (512 * 34 + 2 * 16 * 68) * 4;
    cudaFuncSetAttribute(scan_kernel,
                         cudaFuncAttributeMaxDynamicSharedMemorySize, scan_smem);

    const long long TOT = (long long)TT * BSZ * NF;
    prep_kernel<<<(unsigned)((TOT + 255) / 256), 256>>>(
        x, W_ih, W_hh, b_ih, b_hh,
        b1, g1, be1, rm1, rv1, b2, g2, be2, rm2, rv2, b3, g3, be3, rm3, rv3);

    // U = XIN @ W_ih^T + b_ih
    {
        dim3 grid(NF / 128, (TT * BSZ) / 128);
        mma_gemm_kernel<128,128,2,4,false,false,false><<<grid, 256>>>(
            xint, NF, W_ih, NF, b_ih, nullptr, u, NF, nullptr, 0, NF, NF);
    }

    // persistent scan
    scan_kernel<<<128, 256, scan_smem>>>(W_hh, b_hh);

    // autoencoder over all rows
    {
        dim3 grid1((HID + 127) / 128, (TT * BSZ) / 128);
        mma_gemm_kernel<128,128,2,4,true,false,false><<<grid1, 256>>>(
            hs, NF, W1, NF, d1, a1, z1, HID, nullptr, 0, HID, NF);
        mma_gemm_kernel<128,128,2,4,true,false,false><<<grid1, 256>>>(
            z1, HID, W2, HID, d2, a2, z2, HID, nullptr, 0, HID, HID);
        dim3 grid3(NF / 128, (TT * BSZ) / 128);
        mma_gemm_kernel<128,128,2,4,true,false,false><<<grid3, 256>>>(
            z2, HID, W3, HID, d3, a3, y, NF, nullptr, 0, NF, HID);
    }

    loss1_kernel<<<2048, 256>>>();
    init_dec_kernel<<<(BF + 255) / 256, 256>>>();

    // decoder: 16 steps x 4 mma GEMMs (64x64 tiles, 128 threads)
    {
        dim3 gcell(512 / 64, BSZ / 64);                // (8, 8)
        dim3 ghid((HID + 63) / 64, BSZ / 64);          // (16, 8)
        for (int g = 0; g < MAXG; g++) {
            float* cur  = dxh + (size_t)(g & 1) * BSZ * 1024;
            float* next = dxh + (size_t)((g + 1) & 1) * BSZ * 1024;
            mma_gemm_kernel<64,64,1,4,false,true,false><<<gcell, 128>>>(
                cur, 1024, wc, 1024, bc, nullptr, next + 512, 1024, nullptr, 0, 512, 1024);
            mma_gemm_kernel<64,64,1,4,true,false,false><<<ghid, 128>>>(
                next + 512, 1024, W1, NF, d1, a1, dz1, HID, nullptr, 0, HID, NF);
            mma_gemm_kernel<64,64,1,4,true,false,false><<<ghid, 128>>>(
                dz1, HID, W2, HID, d2, a2, dz2, HID, nullptr, 0, HID, HID);
            mma_gemm_kernel<64,64,1,4,true,false,true><<<gcell, 128>>>(
                dz2, HID, W3, HID, d3, a3, next, 1024,
                xall + (size_t)g * BF, NF, 512, HID);
        }
    }

    finalize_kernel<<<BSZ, 256>>>(x, t, out);
    write_loss_kernel<<<1, 1>>>(out, out_size);
}

// round 14
// speedup vs baseline: 1.6285x; 1.0181x over previous
#include <cuda_runtime.h>
#include <cuda_bf16.h>
#include <math.h>

#define BSZ   512
#define TT    64
#define NF    512
#define HID   1000
#define MAXG  16
#define EPSV  1e-5f
#define BF    (BSZ*NF)

// ---------------- scratch -----------------------------------------------------
__device__ __align__(256) float g_xint[TT*BSZ*NF];
__device__ __align__(256) float g_u   [TT*BSZ*NF];
__device__ __align__(256) float g_hs  [TT*BSZ*NF];
__device__ __align__(256) float g_z1  [TT*BSZ*HID];
__device__ __align__(256) float g_z2  [TT*BSZ*HID];
__device__ __align__(256) float g_y   [TT*BSZ*NF];
__device__ __align__(256) float g_xall[MAXG*BSZ*NF];
__device__ __align__(256) float g_dxh [2*BSZ*1024];
__device__ __align__(256) float g_dz1 [BSZ*HID];
__device__ __align__(256) float g_dz2 [BSZ*HID];
__device__ __align__(256) float g_wc  [512*1024];
__device__ __align__(256) float g_bc  [512];
__device__ __align__(16) float g_a1[HID], g_d1[HID];
__device__ __align__(16) float g_a2[HID], g_d2[HID];
__device__ __align__(16) float g_a3[NF],  g_d3[NF];
__device__ double g_sum1, g_sum2;
__device__ unsigned g_barcnt = 0;
__device__ volatile unsigned g_bargen = 0;

// ---------------- helpers ------------------------------------------------------
__device__ __forceinline__ unsigned f2tf(float f)
{
    unsigned r;
    asm("cvt.rna.tf32.f32 %0, %1;" : "=r"(r) : "f"(f));
    return r;
}

__device__ __forceinline__ void mma_tf32(float* c, const unsigned* a, const unsigned* b)
{
    asm volatile(
        "mma.sync.aligned.m16n8k8.row.col.f32.tf32.tf32.f32 "
        "{%0,%1,%2,%3},{%4,%5,%6,%7},{%8,%9},{%0,%1,%2,%3};"
        : "+f"(c[0]), "+f"(c[1]), "+f"(c[2]), "+f"(c[3])
        : "r"(a[0]), "r"(a[1]), "r"(a[2]), "r"(a[3]), "r"(b[0]), "r"(b[1]));
}

__device__ __forceinline__ void cp_async16(unsigned saddr, const void* gptr, int vb)
{
    asm volatile("cp.async.cg.shared.global [%0], [%1], 16, %2;\n"
                 :: "r"(saddr), "l"(gptr), "r"(vb));
}
__device__ __forceinline__ void cp_commit()
{
    asm volatile("cp.async.commit_group;\n" ::: "memory");
}
__device__ __forceinline__ void cp_wait0()
{
    asm volatile("cp.async.wait_group 0;\n" ::: "memory");
}

// ---------------- prep ---------------------------------------------------------
__global__ void prep_kernel(const float* __restrict__ x,
    const float* W_ih, const float* W_hh, const float* b_ih, const float* b_hh,
    const float* b1, const float* g1, const float* be1, const float* rm1, const float* rv1,
    const float* b2, const float* g2, const float* be2, const float* rm2, const float* rv2,
    const float* b3, const float* g3, const float* be3, const float* rm3, const float* rv3)
{
    long long idx = (long long)blockIdx.x * blockDim.x + threadIdx.x;
    const long long TOT = (long long)TT * BSZ * NF;
    if (idx < TOT) {
        int f = (int)(idx & (NF - 1));
        long long tb = idx >> 9;
        int b = (int)(tb & (BSZ - 1));
        int t = (int)(tb >> 9);
        g_xint[idx] = x[((long long)b * (TT + 1) + t) * NF + f];
    }
    if (idx < 512 * 1024) {
        int n = (int)(idx >> 10), k = (int)(idx & 1023);
        g_wc[idx] = (k < 512) ? W_ih[n * 512 + k] : W_hh[n * 512 + (k - 512)];
    }
    if (idx < HID) {
        float s1 = g1[idx] * rsqrtf(rv1[idx] + EPSV);
        g_a1[idx] = s1;
        g_d1[idx] = s1 * (b1[idx] - rm1[idx]) + be1[idx];
        float s2 = g2[idx] * rsqrtf(rv2[idx] + EPSV);
        g_a2[idx] = s2;
        g_d2[idx] = s2 * (b2[idx] - rm2[idx]) + be2[idx];
    }
    if (idx < NF) {
        float s3 = g3[idx] * rsqrtf(rv3[idx] + EPSV);
        g_a3[idx] = s3;
        g_d3[idx] = s3 * (b3[idx] - rm3[idx]) + be3[idx];
        g_bc[idx] = b_ih[idx] + b_hh[idx];
    }
    if (idx == 0) { g_sum1 = 0.0; g_sum2 = 0.0; g_barcnt = 0; g_bargen = 0; }
}

// ---------------- tf32 tensor-core GEMM with cp.async staging -------------------
template<int BM, int BN, int WM, int WN, bool SCALE, bool TANH, bool DUAL>
__global__ void __launch_bounds__(WM*WN*32) mma_gemm_kernel(
    const float* __restrict__ A, int lda,
    const float* __restrict__ W, int ldw,
    const float* __restrict__ bias, const float* __restrict__ scale,
    float* __restrict__ C, int ldc, float* __restrict__ C2, int ldc2,
    int N, int K)
{
    constexpr int THREADS = WM * WN * 32;
    constexpr int TM = BM / WM;
    constexpr int TN = BN / WN;
    constexpr int FM = TM / 16;
    constexpr int FN = TN / 8;
    constexpr int LDSZ = 20;
    constexpr int ASEG = (BM * 4) / THREADS;
    constexpr int BSEG = (BN * 4) / THREADS;
    static_assert(ASEG >= 1 && BSEG >= 1, "tile/thread mismatch");

    __shared__ __align__(16) float sA[2][BM][LDSZ];
    __shared__ __align__(16) float sB[2][BN][LDSZ];

    const int tid  = threadIdx.x;
    const int lane = tid & 31;
    const int wid  = tid >> 5;
    const int wm   = wid / WN, wn = wid % WN;
    const int g8   = lane >> 2, t4 = lane & 3;

    const int m0 = blockIdx.y * BM;
    const int n0 = blockIdx.x * BN;

    const unsigned sA_u = (unsigned)__cvta_generic_to_shared(&sA[0][0][0]);
    const unsigned sB_u = (unsigned)__cvta_generic_to_shared(&sB[0][0][0]);

    int aRow[ASEG], aKq[ASEG];
    const float* aBase[ASEG];
    #pragma unroll
    for (int l = 0; l < ASEG; l++) {
        int s = tid + l * THREADS;
        aRow[l] = s >> 2;
        aKq[l]  = (s & 3) * 4;
        aBase[l] = A + (long long)(m0 + aRow[l]) * lda;
    }
    int bRow[BSEG], bKq[BSEG];
    const float* bBase[BSEG];
    bool bOk[BSEG];
    #pragma unroll
    for (int l = 0; l < BSEG; l++) {
        int s = tid + l * THREADS;
        bRow[l] = s >> 2;
        bKq[l]  = (s & 3) * 4;
        bOk[l]  = (n0 + bRow[l]) < N;
        bBase[l] = W + (long long)(bOk[l] ? (n0 + bRow[l]) : 0) * ldw;
    }

    const int nch = (K + 15) >> 4;

    auto stage = [&](int buf, int kk) {
        #pragma unroll
        for (int l = 0; l < ASEG; l++) {
            int gk = kk + aKq[l];
            int rem = K - gk;
            int vb = rem >= 4 ? 16 : (rem > 0 ? rem * 4 : 0);
            const float* src = aBase[l] + (vb ? gk : 0);
            unsigned dst = sA_u + (((buf * BM + aRow[l]) * LDSZ) + aKq[l]) * 4;
            cp_async16(dst, src, vb);
        }
        #pragma unroll
        for (int l = 0; l < BSEG; l++) {
            int gk = kk + bKq[l];
            int rem = K - gk;
            int vb = (bOk[l] && rem > 0) ? (rem >= 4 ? 16 : rem * 4) : 0;
            const float* src = bBase[l] + (vb ? gk : 0);
            unsigned dst = sB_u + (((buf * BN + bRow[l]) * LDSZ) + bKq[l]) * 4;
            cp_async16(dst, src, vb);
        }
        cp_commit();
    };

    float acc[FM][FN][4];
    #pragma unroll
    for (int i = 0; i < FM; i++)
        #pragma unroll
        for (int j = 0; j < FN; j++)
            #pragma unroll
            for (int q = 0; q < 4; q++) acc[i][j][q] = 0.0f;

    stage(0, 0);

    for (int c = 0; c < nch; c++) {
        const int buf = c & 1;
        cp_wait0();
        __syncthreads();
        if (c + 1 < nch) stage(buf ^ 1, (c + 1) * 16);

        #pragma unroll
        for (int ks = 0; ks < 16; ks += 8) {
            unsigned af[FM][4], bf[FN][2];
            #pragma unroll
            for (int i = 0; i < FM; i++) {
                int m = wm * TM + 16 * i + g8;
                af[i][0] = f2tf(sA[buf][m    ][ks + t4]);
                af[i][1] = f2tf(sA[buf][m + 8][ks + t4]);
                af[i][2] = f2tf(sA[buf][m    ][ks + t4 + 4]);
                af[i][3] = f2tf(sA[buf][m + 8][ks + t4 + 4]);
            }
            #pragma unroll
            for (int j = 0; j < FN; j++) {
                int n = wn * TN + 8 * j + g8;
                bf[j][0] = f2tf(sB[buf][n][ks + t4]);
                bf[j][1] = f2tf(sB[buf][n][ks + t4 + 4]);
            }
            #pragma unroll
            for (int i = 0; i < FM; i++)
                #pragma unroll
                for (int j = 0; j < FN; j++)
                    mma_tf32(acc[i][j], af[i], bf[j]);
        }
    }

    #pragma unroll
    for (int i = 0; i < FM; i++) {
        int row = m0 + wm * TM + 16 * i + g8;
        #pragma unroll
        for (int j = 0; j < FN; j++) {
            int col = n0 + wn * TN + 8 * j + 2 * t4;
            if (col < N) {
                float2 bi = *(const float2*)(bias + col);
                float2 sc;
                if (SCALE) sc = *(const float2*)(scale + col);
                float v00 = acc[i][j][0], v01 = acc[i][j][1];
                float v10 = acc[i][j][2], v11 = acc[i][j][3];
                if (SCALE) {
                    v00 = v00 * sc.x + bi.x; v01 = v01 * sc.y + bi.y;
                    v10 = v10 * sc.x + bi.x; v11 = v11 * sc.y + bi.y;
                } else {
                    v00 += bi.x; v01 += bi.y; v10 += bi.x; v11 += bi.y;
                }
                if (TANH) { v00 = tanhf(v00); v01 = tanhf(v01);
                            v10 = tanhf(v10); v11 = tanhf(v11); }
                *(float2*)(C + (long long)row * ldc + col)       = make_float2(v00, v01);
                *(float2*)(C + (long long)(row + 8) * ldc + col) = make_float2(v10, v11);
                if (DUAL) {
                    *(float2*)(C2 + (long long)row * ldc2 + col)       = make_float2(v00, v01);
                    *(float2*)(C2 + (long long)(row + 8) * ldc2 + col) = make_float2(v10, v11);
                }
            }
        }
    }
}

// ---------------- persistent tensor-core scan -----------------------------------
__device__ __forceinline__ void grid_barrier(int nb)
{
    __syncthreads();
    if (threadIdx.x == 0) {
        __threadfence();
        unsigned gen = g_bargen;
        if (atomicAdd(&g_barcnt, 1u) == (unsigned)(nb - 1)) {
            g_barcnt = 0;
            __threadfence();
            g_bargen = gen + 1;
        } else {
            while (g_bargen == gen) { }
        }
    }
    __syncthreads();
}

// 128 blocks x 128 threads. Tile 64x32. Whh rows [n0,n0+32) held in smem
// pre-rounded to tf32 for all 64 steps (stride 532 == 20 mod 32: conflict-free).
#define S_LDW 532
__global__ void __launch_bounds__(128) scan_kernel(const float* __restrict__ Whh,
                                                   const float* __restrict__ bhh)
{
    extern __shared__ float sm[];
    float* sW = sm;                    // [32][S_LDW], tf32 bit patterns
    float* sA = sm + 32 * S_LDW;       // [2][64][20]

    const int tid  = threadIdx.x;
    const int lane = tid & 31;
    const int wn   = tid >> 5;         // 4 warps, WN=4
    const int g8   = lane >> 2, t4 = lane & 3;
    const int n0 = (blockIdx.x & 15) * 32;
    const int m0 = (blockIdx.x >> 4) * 64;

    for (int idx = tid; idx < 32 * 512; idx += 128) {
        int n = idx >> 9, k = idx & 511;
        sW[n * S_LDW + k] = __uint_as_float(f2tf(Whh[(n0 + n) * 512 + k]));
    }
    const int colb = n0 + wn * 8 + 2 * t4;
    const float2 bh = *(const float2*)(bhh + colb);
    __syncthreads();

    const unsigned sA_u = (unsigned)__cvta_generic_to_shared(sA);
    int aRow[2], aKq[2];
    #pragma unroll
    for (int l = 0; l < 2; l++) {
        int s = tid + l * 128;
        aRow[l] = s >> 2;
        aKq[l]  = (s & 3) * 4;
    }
    const unsigned* sWb = (const unsigned*)(sW + (wn * 8 + g8) * S_LDW);

    for (int t = 0; t < TT; t++) {
        float acc[4][4];
        #pragma unroll
        for (int i = 0; i < 4; i++)
            #pragma unroll
            for (int q = 0; q < 4; q++) acc[i][q] = 0.0f;

        if (t > 0) {
            const float* H = g_hs + (long long)(t - 1) * BF;
            auto stage = [&](int buf, int c) {
                #pragma unroll
                for (int l = 0; l < 2; l++) {
                    const float* src = H + (long long)(m0 + aRow[l]) * 512 + c * 16 + aKq[l];
                    unsigned dst = sA_u + (((buf * 64 + aRow[l]) * 20) + aKq[l]) * 4;
                    cp_async16(dst, src, 16);
                }
                cp_commit();
            };
            stage(0, 0);
            for (int c = 0; c < 32; c++) {
                const int buf = c & 1;
                cp_wait0();
                __syncthreads();
                if (c + 1 < 32) stage(buf ^ 1, c + 1);

                #pragma unroll
                for (int ks = 0; ks < 16; ks += 8) {
                    unsigned af[4][4], bf[2];
                    #pragma unroll
                    for (int i = 0; i < 4; i++) {
                        int m = 16 * i + g8;
                        af[i][0] = f2tf(sA[(buf * 64 + m    ) * 20 + ks + t4]);
                        af[i][1] = f2tf(sA[(buf * 64 + m + 8) * 20 + ks + t4]);
                        af[i][2] = f2tf(sA[(buf * 64 + m    ) * 20 + ks + t4 + 4]);
                        af[i][3] = f2tf(sA[(buf * 64 + m + 8) * 20 + ks + t4 + 4]);
                    }
                    bf[0] = sWb[c * 16 + ks + t4];
                    bf[1] = sWb[c * 16 + ks + t4 + 4];
                    #pragma unroll
                    for (int i = 0; i < 4; i++)
                        mma_tf32(acc[i], af[i], bf);
                }
                __syncthreads();
            }
        }

        const float* Ut = g_u + (long long)t * BF;
        float* Ht = g_hs + (long long)t * BF;
        #pragma unroll
        for (int i = 0; i < 4; i++) {
            int row = m0 + 16 * i + g8;
            long long off0 = (long long)row * 512 + colb;
            long long off1 = off0 + 8 * 512;
            float2 u0 = *(const float2*)(Ut + off0);
            float2 u1 = *(const float2*)(Ut + off1);
            float2 h0, h1;
            h0.x = tanhf(acc[i][0] + u0.x + bh.x);
            h0.y = tanhf(acc[i][1] + u0.y + bh.y);
            h1.x = tanhf(acc[i][2] + u1.x + bh.x);
            h1.y = tanhf(acc[i][3] + u1.y + bh.y);
            *(float2*)(Ht + off0) = h0;
            *(float2*)(Ht + off1) = h1;
        }
        grid_barrier(gridDim.x);
    }
}

// ---------------- reductions / misc --------------------------------------------
__device__ __forceinline__ double block_reduce(double v)
{
    __shared__ double sh[32];
    #pragma unroll
    for (int o = 16; o > 0; o >>= 1) v += __shfl_down_sync(0xffffffffu, v, o);
    int lane = threadIdx.x & 31, w = threadIdx.x >> 5;
    if (lane == 0) sh[w] = v;
    __syncthreads();
    if (w == 0) {
        int nw = (blockDim.x + 31) >> 5;
        v = (lane < nw) ? sh[lane] : 0.0;
        #pragma unroll
        for (int o = 16; o > 0; o >>= 1) v += __shfl_down_sync(0xffffffffu, v, o);
    }
    return v;
}

__global__ void loss1_kernel()
{
    const long long TOT = (long long)(TT - 1) * BSZ * NF;
    double local = 0.0;
    for (long long idx = (long long)blockIdx.x * blockDim.x + threadIdx.x;
         idx < TOT; idx += (long long)gridDim.x * blockDim.x) {
        float d = g_y[idx] - g_xint[idx + BF];
        local += (double)d * (double)d;
    }
    double s = block_reduce(local);
    if (threadIdx.x == 0) atomicAdd(&g_sum1, s);
}

__global__ void init_dec_kernel()
{
    int idx = blockIdx.x * blockDim.x + threadIdx.x;
    if (idx < BF) {
        int b = idx >> 9, f = idx & 511;
        g_dxh[(long long)b * 1024 + f]       = g_y [(long long)63 * BF + idx];
        g_dxh[(long long)b * 1024 + 512 + f] = g_hs[(long long)63 * BF + idx];
    }
}

__global__ void finalize_kernel(const float* __restrict__ x,
                                const int* __restrict__ t,
                                float* __restrict__ out)
{
    int b = blockIdx.x;
    int g = t[b] - 1;
    const float* xp = g_xall + ((long long)g * BSZ + b) * NF;
    const float* xf = x + ((long long)b * (TT + 1) + TT) * NF;
    double local = 0.0;
    for (int f = threadIdx.x; f < NF; f += blockDim.x) {
        float v = xp[f];
        out[(long long)b * NF + f] = v;
        float d = v - xf[f];
        local += (double)d * (double)d;
    }
    double s = block_reduce(local);
    if (threadIdx.x == 0) atomicAdd(&g_sum2, s);
}

__global__ void write_loss_kernel(float* __restrict__ out, int out_size)
{
    if (out_size > BSZ * NF) {
        double n1 = (double)(TT - 1) * BSZ * NF;
        double n2 = (double)BSZ * NF;
        double loss = g_sum1 / (n1 * n1) + g_sum2 / (n2 * n2);
        out[BSZ * NF] = (float)loss;
    }
}

// ---------------- launch --------------------------------------------------------
extern "C" void kernel_launch(void* const* d_in, const int* in_sizes, int n_in,
                              void* d_out, int out_size)
{
    const float* x    = (const float*)d_in[0];
    const int*   t    = (const int*)  d_in[1];
    const float* W_ih = (const float*)d_in[2];
    const float* W_hh = (const float*)d_in[3];
    const float* b_ih = (const float*)d_in[4];
    const float* b_hh = (const float*)d_in[5];
    const float* W1   = (const float*)d_in[6];
    const float* b1   = (const float*)d_in[7];
    const float* g1   = (const float*)d_in[8];
    const float* be1  = (const float*)d_in[9];
    const float* rm1  = (const float*)d_in[10];
    const float* rv1  = (const float*)d_in[11];
    const float* W2   = (const float*)d_in[12];
    const float* b2   = (const float*)d_in[13];
    const float* g2   = (const float*)d_in[14];
    const float* be2  = (const float*)d_in[15];
    const float* rm2  = (const float*)d_in[16];
    const float* rv2  = (const float*)d_in[17];
    const float* W3   = (const float*)d_in[18];
    const float* b3   = (const float*)d_in[19];
    const float* g3   = (const float*)d_in[20];
    const float* be3  = (const float*)d_in[21];
    const float* rm3  = (const float*)d_in[22];
    const float* rv3  = (const float*)d_in[23];
    float* out = (float*)d_out;

    float *xint, *u, *hs, *z1, *z2, *y, *xall, *dxh, *dz1, *dz2, *wc, *bc;
    float *a1, *d1, *a2, *d2, *a3, *d3;
    cudaGetSymbolAddress((void**)&xint, g_xint);
    cudaGetSymbolAddress((void**)&u,    g_u);
    cudaGetSymbolAddress((void**)&hs,   g_hs);
    cudaGetSymbolAddress((void**)&z1,   g_z1);
    cudaGetSymbolAddress((void**)&z2,   g_z2);
    cudaGetSymbolAddress((void**)&y,    g_y);
    cudaGetSymbolAddress((void**)&xall, g_xall);
    cudaGetSymbolAddress((void**)&dxh,  g_dxh);
    cudaGetSymbolAddress((void**)&dz1,  g_dz1);
    cudaGetSymbolAddress((void**)&dz2,  g_dz2);
    cudaGetSymbolAddress((void**)&wc,   g_wc);
    cudaGetSymbolAddress((void**)&bc,   g_bc);
    cudaGetSymbolAddress((void**)&a1,   g_a1);
    cudaGetSymbolAddress((void**)&d1,   g_d1);
    cudaGetSymbolAddress((void**)&a2,   g_a2);
    cudaGetSymbolAddress((void**)&d2,   g_d2);
    cudaGetSymbolAddress((void**)&a3,   g_a3);
    cudaGetSymbolAddress((void**)&d3,   g_d3);

    const int scan_smem = (32 * S_LDW + 2 * 64 * 20) * 4;   // 78336 B
    cudaFuncSetAttribute(scan_kernel,
                         cudaFuncAttributeMaxDynamicSharedMemorySize, scan_smem);

    const long long TOT = (long long)TT * BSZ * NF;
    prep_kernel<<<(unsigned)((TOT + 255) / 256), 256>>>(
        x, W_ih, W_hh, b_ih, b_hh,
        b1, g1, be1, rm1, rv1, b2, g2, be2, rm2, rv2, b3, g3, be3, rm3, rv3);

    // U = XIN @ W_ih^T + b_ih
    {
        dim3 grid(NF / 128, (TT * BSZ) / 128);
        mma_gemm_kernel<128,128,2,4,false,false,false><<<grid, 256>>>(
            xint, NF, W_ih, NF, b_ih, nullptr, u, NF, nullptr, 0, NF, NF);
    }

    // persistent tensor-core scan
    scan_kernel<<<128, 128, scan_smem>>>(W_hh, b_hh);

    // autoencoder over all rows
    {
        dim3 grid1((HID + 127) / 128, (TT * BSZ) / 128);
        mma_gemm_kernel<128,128,2,4,true,false,false><<<grid1, 256>>>(
            hs, NF, W1, NF, d1, a1, z1, HID, nullptr, 0, HID, NF);
        mma_gemm_kernel<128,128,2,4,true,false,false><<<grid1, 256>>>(
            z1, HID, W2, HID, d2, a2, z2, HID, nullptr, 0, HID, HID);
        dim3 grid3(NF / 128, (TT * BSZ) / 128);
        mma_gemm_kernel<128,128,2,4,true,false,false><<<grid3, 256>>>(
            z2, HID, W3, HID, d3, a3, y, NF, nullptr, 0, NF, HID);
    }

    loss1_kernel<<<2048, 256>>>();
    init_dec_kernel<<<(BF + 255) / 256, 256>>>();

    // decoder: 16 steps x 4 mma GEMMs (64x64 tiles, 128 threads)
    {
        dim3 gcell(512 / 64, BSZ / 64);                // (8, 8)
        dim3 ghid((HID + 63) / 64, BSZ / 64);          // (16, 8)
        for (int g = 0; g < MAXG; g++) {
            float* cur  = dxh + (size_t)(g & 1) * BSZ * 1024;
            float* next = dxh + (size_t)((g + 1) & 1) * BSZ * 1024;
            mma_gemm_kernel<64,64,1,4,false,true,false><<<gcell, 128>>>(
                cur, 1024, wc, 1024, bc, nullptr, next + 512, 1024, nullptr, 0, 512, 1024);
            mma_gemm_kernel<64,64,1,4,true,false,false><<<ghid, 128>>>(
                next + 512, 1024, W1, NF, d1, a1, dz1, HID, nullptr, 0, HID, NF);
            mma_gemm_kernel<64,64,1,4,true,false,false><<<ghid, 128>>>(
                dz1, HID, W2, HID, d2, a2, dz2, HID, nullptr, 0, HID, HID);
            mma_gemm_kernel<64,64,1,4,true,false,true><<<gcell, 128>>>(
                dz2, HID, W3, HID, d3, a3, next, 1024,
                xall + (size_t)g * BF, NF, 512, HID);
        }
    }

    finalize_kernel<<<BSZ, 256>>>(x, t, out);
    write_loss_kernel<<<1, 1>>>(out, out_size);
}